// round 7
// baseline (speedup 1.0000x reference)
#include <cuda_runtime.h>
#include <cuda_bf16.h>
#include <cstdint>

#define N_NODES 50000
#define N_EDGES 800000
#define D 128
#define N_LAYERS 3
#define N_GRAPHS 512
#define ND (N_NODES * D)

#define SCAN_BLK 512
#define SCAN_NBLK ((N_NODES + SCAN_BLK - 1) / SCAN_BLK)   // 98

#define FRAG_PER_LAYER (D * D)    // 16384 floats per layer per split

// ---------------- scratch (device globals; no allocation allowed) ----------------
__device__ float  g_h[ND];                  // post-GEMM features
__device__ float  g_x[ND];                  // layer output buffer
__device__ float  g_wfhi[N_LAYERS * FRAG_PER_LAYER];  // W tf32-hi, B-fragment order
__device__ float  g_wflo[N_LAYERS * FRAG_PER_LAYER];  // W tf32-lo, B-fragment order
__device__ float  g_dis[N_NODES];           // deg^{-1/2} (incl. self-loop)
__device__ int    g_deg[N_NODES];           // in-degree (edges only)
__device__ int    g_cur[N_NODES];           // placement cursor
__device__ int    g_off[N_NODES + 1];       // CSR offsets (by dst)
__device__ int    g_bsum[SCAN_NBLK];        // scan block sums
__device__ float2 g_em[N_EDGES];            // per-slot: (src as int bits, norm)
__device__ float  g_gsum[N_GRAPHS];
__device__ int    g_gcnt[N_GRAPHS];

// ---------------- tf32 split helper ----------------
__device__ __forceinline__ void tf32_split(float v, uint32_t& hi, uint32_t& lo) {
    asm("cvt.rna.tf32.f32 %0, %1;" : "=r"(hi) : "f"(v));
    float r = v - __uint_as_float(hi);
    asm("cvt.rna.tf32.f32 %0, %1;" : "=r"(lo) : "f"(r));
}

#define MMA_TF32(c, a0, a1, a2, a3, b0, b1) \
    asm volatile("mma.sync.aligned.m16n8k8.row.col.f32.tf32.tf32.f32 " \
        "{%0,%1,%2,%3}, {%4,%5,%6,%7}, {%8,%9}, {%0,%1,%2,%3};" \
        : "+f"(c[0]), "+f"(c[1]), "+f"(c[2]), "+f"(c[3]) \
        : "r"(a0), "r"(a1), "r"(a2), "r"(a3), "r"(b0), "r"(b1))

// ---------------- zero ----------------
__global__ void zero_misc_k() {
    int i = blockIdx.x * blockDim.x + threadIdx.x;
    if (i < N_NODES) { g_deg[i] = 0; g_cur[i] = 0; }
    if (i < N_GRAPHS) { g_gsum[i] = 0.f; g_gcnt[i] = 0; }
}

// ---------------- W -> tf32 split fragments (B-fragment order for m16n8k8) ----------------
__global__ void wfrag_k(const float* __restrict__ Ws) {
    int i = blockIdx.x * blockDim.x + threadIdx.x;
    if (i >= N_LAYERS * D * D) return;
    int l = i / (D * D);
    int rem = i - l * (D * D);
    int o = rem / D;           // Ws[l][o][k]: output col
    int k = rem - o * D;       // reduction index
    uint32_t hi, lo;
    tf32_split(Ws[i], hi, lo);
    int k0 = k >> 3, kin = k & 7;
    int tg = kin & 3, half = kin >> 2;
    int nt = o >> 3, gg = o & 7;
    int lane = gg * 4 + tg;
    int idx = (((k0 * 16 + nt) * 32) + lane) * 2 + half;
    g_wfhi[l * FRAG_PER_LAYER + idx] = __uint_as_float(hi);
    g_wflo[l * FRAG_PER_LAYER + idx] = __uint_as_float(lo);
}

// ---------------- degree histogram ----------------
__global__ void deg_k(const int* __restrict__ ei) {
    int e = blockIdx.x * blockDim.x + threadIdx.x;
    if (e >= N_EDGES) return;
    atomicAdd(&g_deg[ei[N_EDGES + e]], 1);
}

// ---------------- scan1 (also computes dis) ----------------
__global__ void scan1_k() {
    __shared__ int sm[SCAN_BLK];
    int tid = threadIdx.x;
    int gid = blockIdx.x * SCAN_BLK + tid;
    int v = 0;
    if (gid < N_NODES) {
        v = g_deg[gid];
        g_dis[gid] = rsqrtf((float)(v + 1));   // +1 self loop
    }
    sm[tid] = v;
    __syncthreads();
    #pragma unroll
    for (int o = 1; o < SCAN_BLK; o <<= 1) {
        int t = (tid >= o) ? sm[tid - o] : 0;
        __syncthreads();
        sm[tid] += t;
        __syncthreads();
    }
    if (gid < N_NODES) g_off[gid] = sm[tid] - v;   // exclusive, block-local
    if (tid == SCAN_BLK - 1) g_bsum[blockIdx.x] = sm[tid];
}
__global__ void scan2_k() {
    if (threadIdx.x == 0) {
        int run = 0;
        for (int i = 0; i < SCAN_NBLK; i++) {
            int t = g_bsum[i];
            g_bsum[i] = run;
            run += t;
        }
    }
}
__global__ void scan3_k() {
    int gid = blockIdx.x * blockDim.x + threadIdx.x;
    if (gid < N_NODES) g_off[gid] += g_bsum[gid / SCAN_BLK];
    if (gid == 0) g_off[N_NODES] = N_EDGES;
}

// ---------------- counting-sort placement: group edges by dst ----------------
__global__ void place_k(const int* __restrict__ ei) {
    int e = blockIdx.x * blockDim.x + threadIdx.x;
    if (e >= N_EDGES) return;
    int r = ei[e];
    int c = ei[N_EDGES + e];
    int idx = g_off[c] + atomicAdd(&g_cur[c], 1);
    g_em[idx] = make_float2(__int_as_float(r), g_dis[r] * g_dis[c]);
}

// ---------------- tensor-core GEMM: H = X @ W^T via split-tf32 (3 mma) ----------------
// block: 256 threads (8 warps), 128 rows x 128 cols, full K=128.
// smem: xs[128][132] fp32 only (67.6 KB). B fragments read from global via __ldg
// (perfectly coalesced 256B/warp lines; L1-resident after first warp streams them).
#define XS_STRIDE 132
__global__ void __launch_bounds__(256)
gemm_tc_k(const float* __restrict__ X, const float* __restrict__ Fh,
          const float* __restrict__ Fl, float* __restrict__ H, int n) {
    extern __shared__ float sm[];
    float* xs = sm;                        // [128][132]

    int tid = threadIdx.x;
    int row0 = blockIdx.x * 128;

    // load X tile into padded smem (float4 coalesced)
    #pragma unroll
    for (int it = 0; it < 16; it++) {
        int i = tid + it * 256;            // 4096 float4s
        int r = i >> 5;
        int c4 = (i & 31) << 2;
        float4 v = make_float4(0.f, 0.f, 0.f, 0.f);
        int rg = row0 + r;
        if (rg < n) v = *(const float4*)(X + rg * D + c4);
        *(float4*)(xs + r * XS_STRIDE + c4) = v;
    }
    __syncthreads();

    int wid = tid >> 5;
    int lane = tid & 31;
    int g = lane >> 2, tig = lane & 3;
    int warpRow = wid * 16;

    float acc[16][4];
    #pragma unroll
    for (int nt = 0; nt < 16; nt++) {
        acc[nt][0] = 0.f; acc[nt][1] = 0.f; acc[nt][2] = 0.f; acc[nt][3] = 0.f;
    }

    const float* rowA0 = xs + (warpRow + g) * XS_STRIDE;
    const float* rowA1 = xs + (warpRow + g + 8) * XS_STRIDE;

    #pragma unroll 2
    for (int k0 = 0; k0 < 16; k0++) {
        int k = k0 * 8;
        float a0f = rowA0[k + tig];
        float a1f = rowA1[k + tig];
        float a2f = rowA0[k + tig + 4];
        float a3f = rowA1[k + tig + 4];
        uint32_t ah0, ah1, ah2, ah3, al0, al1, al2, al3;
        tf32_split(a0f, ah0, al0);
        tf32_split(a1f, ah1, al1);
        tf32_split(a2f, ah2, al2);
        tf32_split(a3f, ah3, al3);

        const float2* bh = (const float2*)Fh + (k0 * 16) * 32 + lane;
        const float2* bl = (const float2*)Fl + (k0 * 16) * 32 + lane;

        #pragma unroll
        for (int nt = 0; nt < 16; nt++) {
            float2 h2 = __ldg(bh + nt * 32);
            float2 l2 = __ldg(bl + nt * 32);
            uint32_t bh0 = __float_as_uint(h2.x), bh1 = __float_as_uint(h2.y);
            uint32_t bl0 = __float_as_uint(l2.x), bl1 = __float_as_uint(l2.y);
            MMA_TF32(acc[nt], ah0, ah1, ah2, ah3, bh0, bh1);
            MMA_TF32(acc[nt], ah0, ah1, ah2, ah3, bl0, bl1);
            MMA_TF32(acc[nt], al0, al1, al2, al3, bh0, bh1);
        }
    }

    // store: c0,c1 -> row g, cols 2tig,2tig+1; c2,c3 -> row g+8
    int r1 = row0 + warpRow + g;
    int r2 = r1 + 8;
    #pragma unroll
    for (int nt = 0; nt < 16; nt++) {
        int col = nt * 8 + tig * 2;
        if (r1 < n) *(float2*)(H + r1 * D + col) = make_float2(acc[nt][0], acc[nt][1]);
        if (r2 < n) *(float2*)(H + r2 * D + col) = make_float2(acc[nt][2], acc[nt][3]);
    }
}

// ---------------- fused gather + self-loop + bias + relu (atomic-free) ----------------
__global__ void gather_k(const float* __restrict__ bias) {
    int gt = blockIdx.x * blockDim.x + threadIdx.x;
    int c = gt >> 5;
    int lane = gt & 31;
    if (c >= N_NODES) return;

    int s = g_off[c];
    int e = g_off[c + 1];
    float4 acc = make_float4(0.f, 0.f, 0.f, 0.f);

    int i = s;
    for (; i + 4 <= e; i += 4) {
        float2 m0 = g_em[i + 0];
        float2 m1 = g_em[i + 1];
        float2 m2 = g_em[i + 2];
        float2 m3 = g_em[i + 3];
        const float4 v0 = *(const float4*)(g_h + (size_t)__float_as_int(m0.x) * D + lane * 4);
        const float4 v1 = *(const float4*)(g_h + (size_t)__float_as_int(m1.x) * D + lane * 4);
        const float4 v2 = *(const float4*)(g_h + (size_t)__float_as_int(m2.x) * D + lane * 4);
        const float4 v3 = *(const float4*)(g_h + (size_t)__float_as_int(m3.x) * D + lane * 4);
        acc.x += m0.y * v0.x + m1.y * v1.x + m2.y * v2.x + m3.y * v3.x;
        acc.y += m0.y * v0.y + m1.y * v1.y + m2.y * v2.y + m3.y * v3.y;
        acc.z += m0.y * v0.z + m1.y * v1.z + m2.y * v2.z + m3.y * v3.z;
        acc.w += m0.y * v0.w + m1.y * v1.w + m2.y * v2.w + m3.y * v3.w;
    }
    for (; i < e; i++) {
        float2 m = g_em[i];
        const float4 v = *(const float4*)(g_h + (size_t)__float_as_int(m.x) * D + lane * 4);
        acc.x += m.y * v.x; acc.y += m.y * v.y; acc.z += m.y * v.z; acc.w += m.y * v.w;
    }

    float d = g_dis[c];
    float d2 = d * d;
    float4 h = *(const float4*)(g_h + (size_t)c * D + lane * 4);
    float4 b = ((const float4*)bias)[lane];
    float4 o;
    o.x = fmaxf(acc.x + d2 * h.x + b.x, 0.f);
    o.y = fmaxf(acc.y + d2 * h.y + b.y, 0.f);
    o.z = fmaxf(acc.z + d2 * h.z + b.z, 0.f);
    o.w = fmaxf(acc.w + d2 * h.w + b.w, 0.f);
    *(float4*)(g_x + (size_t)c * D + lane * 4) = o;
}

// ---------------- pooling ----------------
__global__ void pool_k(const int* __restrict__ batch, const float* __restrict__ lw) {
    int gt = blockIdx.x * blockDim.x + threadIdx.x;
    int node = gt >> 5;
    int lane = gt & 31;
    if (node >= N_NODES) return;
    float4 xv = ((const float4*)g_x)[node * 32 + lane];
    float4 wv = ((const float4*)lw)[lane];
    float s = xv.x * wv.x + xv.y * wv.y + xv.z * wv.z + xv.w * wv.w;
    #pragma unroll
    for (int o = 16; o > 0; o >>= 1) s += __shfl_xor_sync(0xFFFFFFFFu, s, o);
    if (lane == 0) {
        int g = batch[node];
        atomicAdd(&g_gsum[g], s);
        atomicAdd(&g_gcnt[g], 1);
    }
}

__global__ void final_k(const float* __restrict__ lb, float* __restrict__ out) {
    int g = blockIdx.x * blockDim.x + threadIdx.x;
    if (g >= N_GRAPHS) return;
    float c = fmaxf((float)g_gcnt[g], 1.0f);
    out[g] = g_gsum[g] / c + lb[0];
}

// ---------------- launcher ----------------
extern "C" void kernel_launch(void* const* d_in, const int* in_sizes, int n_in,
                              void* d_out, int out_size) {
    const float* x    = (const float*)d_in[0];
    const int*   ei   = (const int*)d_in[1];    // int32 (JAX x64 disabled)
    const int*   bat  = (const int*)d_in[2];
    const float* Ws   = (const float*)d_in[3];
    const float* bs   = (const float*)d_in[4];
    const float* lw   = (const float*)d_in[5];
    const float* lb   = (const float*)d_in[6];
    float*       out  = (float*)d_out;

    const int gemm_smem = (128 * XS_STRIDE) * (int)sizeof(float);   // 67.6 KB

    static bool attr_set = false;
    if (!attr_set) {
        cudaFuncSetAttribute(gemm_tc_k, cudaFuncAttributeMaxDynamicSharedMemorySize,
                             gemm_smem);
        attr_set = true;
    }

    float *h_p, *x_p, *wfhi_p, *wflo_p;
    cudaGetSymbolAddress((void**)&h_p,    g_h);
    cudaGetSymbolAddress((void**)&x_p,    g_x);
    cudaGetSymbolAddress((void**)&wfhi_p, g_wfhi);
    cudaGetSymbolAddress((void**)&wflo_p, g_wflo);

    // prep
    zero_misc_k<<<(N_NODES + 255) / 256, 256>>>();
    wfrag_k<<<(N_LAYERS * D * D + 255) / 256, 256>>>(Ws);
    deg_k<<<(N_EDGES + 255) / 256, 256>>>(ei);
    scan1_k<<<SCAN_NBLK, SCAN_BLK>>>();
    scan2_k<<<1, 32>>>();
    scan3_k<<<(N_NODES + 255) / 256, 256>>>();
    place_k<<<(N_EDGES + 255) / 256, 256>>>(ei);

    // layers
    const int gemm_blocks = (N_NODES + 127) / 128;
    const int gather_blocks = (N_NODES * 32 + 255) / 256;

    for (int l = 0; l < N_LAYERS; l++) {
        const float* xin = (l == 0) ? x : x_p;
        gemm_tc_k<<<gemm_blocks, 256, gemm_smem>>>(
            xin, wfhi_p + l * FRAG_PER_LAYER, wflo_p + l * FRAG_PER_LAYER, h_p, N_NODES);
        gather_k<<<gather_blocks, 256>>>(bs + l * D);
    }

    // pooling + output
    pool_k<<<(N_NODES * 32 + 255) / 256, 256>>>(bat, lw);
    final_k<<<(N_GRAPHS + 255) / 256, 256>>>(lb, out);
}

// round 8
// speedup vs baseline: 1.2511x; 1.2511x over previous
#include <cuda_runtime.h>
#include <cuda_bf16.h>
#include <cstdint>

#define N_NODES 50000
#define N_EDGES 800000
#define D 128
#define N_LAYERS 3
#define N_GRAPHS 512
#define ND (N_NODES * D)

#define SCAN_BLK 512
#define SCAN_NBLK ((N_NODES + SCAN_BLK - 1) / SCAN_BLK)   // 98

#define FRAG4_PER_LAYER (D * D / 2)   // 8192 float4s per layer (hi+lo interleaved)

// ---------------- scratch (device globals; no allocation allowed) ----------------
__device__ float  g_h[ND];                  // post-GEMM features
__device__ float  g_x[ND];                  // layer output buffer
__device__ float4 g_wf[N_LAYERS * FRAG4_PER_LAYER];  // W frags: (bh0,bh1,bl0,bl1)
__device__ float  g_dis[N_NODES];           // deg^{-1/2} (incl. self-loop)
__device__ int    g_deg[N_NODES];           // in-degree (edges only)
__device__ int    g_cur[N_NODES];           // placement cursor
__device__ int    g_off[N_NODES + 1];       // CSR offsets (by dst)
__device__ int    g_bsum[SCAN_NBLK];        // scan block sums
__device__ float2 g_em[N_EDGES];            // per-slot: (src as int bits, norm)
__device__ float  g_gsum[N_GRAPHS];
__device__ int    g_gcnt[N_GRAPHS];

// ---------------- tf32 split helper ----------------
__device__ __forceinline__ void tf32_split(float v, uint32_t& hi, uint32_t& lo) {
    asm("cvt.rna.tf32.f32 %0, %1;" : "=r"(hi) : "f"(v));
    float r = v - __uint_as_float(hi);
    asm("cvt.rna.tf32.f32 %0, %1;" : "=r"(lo) : "f"(r));
}

#define MMA_TF32(c, a0, a1, a2, a3, b0, b1) \
    asm volatile("mma.sync.aligned.m16n8k8.row.col.f32.tf32.tf32.f32 " \
        "{%0,%1,%2,%3}, {%4,%5,%6,%7}, {%8,%9}, {%0,%1,%2,%3};" \
        : "+f"(c[0]), "+f"(c[1]), "+f"(c[2]), "+f"(c[3]) \
        : "r"(a0), "r"(a1), "r"(a2), "r"(a3), "r"(b0), "r"(b1))

// ---------------- zero ----------------
__global__ void zero_misc_k() {
    int i = blockIdx.x * blockDim.x + threadIdx.x;
    if (i < N_NODES) { g_deg[i] = 0; g_cur[i] = 0; }
    if (i < N_GRAPHS) { g_gsum[i] = 0.f; g_gcnt[i] = 0; }
}

// ---------------- W -> interleaved tf32 split fragments ----------------
// float4 slot (k0,nt,lane) holds (hi_half0, hi_half1, lo_half0, lo_half1).
// This thread (one (l,o,k)) writes hi at scalar ofs +half, lo at +2+half.
__global__ void wfrag_k(const float* __restrict__ Ws) {
    int i = blockIdx.x * blockDim.x + threadIdx.x;
    if (i >= N_LAYERS * D * D) return;
    int l = i / (D * D);
    int rem = i - l * (D * D);
    int o = rem / D;           // Ws[l][o][k]: output col
    int k = rem - o * D;       // reduction index
    uint32_t hi, lo;
    tf32_split(Ws[i], hi, lo);
    int k0 = k >> 3, kin = k & 7;
    int tg = kin & 3, half = kin >> 2;
    int nt = o >> 3, gg = o & 7;
    int lane = gg * 4 + tg;
    int idx4 = (k0 * 16 + nt) * 32 + lane;            // float4 index within layer
    float* base = (float*)(g_wf + l * FRAG4_PER_LAYER + idx4);
    base[half]     = __uint_as_float(hi);
    base[2 + half] = __uint_as_float(lo);
}

// ---------------- degree histogram ----------------
__global__ void deg_k(const int* __restrict__ ei) {
    int e = blockIdx.x * blockDim.x + threadIdx.x;
    if (e >= N_EDGES) return;
    atomicAdd(&g_deg[ei[N_EDGES + e]], 1);
}

// ---------------- scan1 (also computes dis) ----------------
__global__ void scan1_k() {
    __shared__ int sm[SCAN_BLK];
    int tid = threadIdx.x;
    int gid = blockIdx.x * SCAN_BLK + tid;
    int v = 0;
    if (gid < N_NODES) {
        v = g_deg[gid];
        g_dis[gid] = rsqrtf((float)(v + 1));   // +1 self loop
    }
    sm[tid] = v;
    __syncthreads();
    #pragma unroll
    for (int o = 1; o < SCAN_BLK; o <<= 1) {
        int t = (tid >= o) ? sm[tid - o] : 0;
        __syncthreads();
        sm[tid] += t;
        __syncthreads();
    }
    if (gid < N_NODES) g_off[gid] = sm[tid] - v;   // exclusive, block-local
    if (tid == SCAN_BLK - 1) g_bsum[blockIdx.x] = sm[tid];
}
__global__ void scan2_k() {
    if (threadIdx.x == 0) {
        int run = 0;
        for (int i = 0; i < SCAN_NBLK; i++) {
            int t = g_bsum[i];
            g_bsum[i] = run;
            run += t;
        }
    }
}
__global__ void scan3_k() {
    int gid = blockIdx.x * blockDim.x + threadIdx.x;
    if (gid < N_NODES) g_off[gid] += g_bsum[gid / SCAN_BLK];
    if (gid == 0) g_off[N_NODES] = N_EDGES;
}

// ---------------- counting-sort placement: group edges by dst ----------------
__global__ void place_k(const int* __restrict__ ei) {
    int e = blockIdx.x * blockDim.x + threadIdx.x;
    if (e >= N_EDGES) return;
    int r = ei[e];
    int c = ei[N_EDGES + e];
    int idx = g_off[c] + atomicAdd(&g_cur[c], 1);
    g_em[idx] = make_float2(__int_as_float(r), g_dis[r] * g_dis[c]);
}

// ---------------- tensor-core GEMM: H = X @ W^T via split-tf32 (3 mma) ----------------
// block: 256 threads (8 warps), 128 rows x 128 cols, full K=128.
// smem: X tile only (67.6 KB). B fragments: ONE coalesced LDG.128 per (k0,nt)
// delivering (bh0,bh1,bl0,bl1) — 4x fewer LSU issues than split hi/lo arrays.
#define XS_STRIDE 132
__global__ void __launch_bounds__(256)
gemm_tc_k(const float* __restrict__ X, const float4* __restrict__ Fr,
          float* __restrict__ H, int n) {
    extern __shared__ float sm[];
    float* xs = sm;                        // [128][132]

    int tid = threadIdx.x;
    int row0 = blockIdx.x * 128;

    // load X tile into padded smem (float4 coalesced)
    #pragma unroll
    for (int it = 0; it < 16; it++) {
        int i = tid + it * 256;            // 4096 float4s
        int r = i >> 5;
        int c4 = (i & 31) << 2;
        float4 v = make_float4(0.f, 0.f, 0.f, 0.f);
        int rg = row0 + r;
        if (rg < n) v = *(const float4*)(X + rg * D + c4);
        *(float4*)(xs + r * XS_STRIDE + c4) = v;
    }
    __syncthreads();

    int wid = tid >> 5;
    int lane = tid & 31;
    int g = lane >> 2, tig = lane & 3;
    int warpRow = wid * 16;

    float acc[16][4];
    #pragma unroll
    for (int nt = 0; nt < 16; nt++) {
        acc[nt][0] = 0.f; acc[nt][1] = 0.f; acc[nt][2] = 0.f; acc[nt][3] = 0.f;
    }

    const float* rowA0 = xs + (warpRow + g) * XS_STRIDE;
    const float* rowA1 = xs + (warpRow + g + 8) * XS_STRIDE;

    #pragma unroll 2
    for (int k0 = 0; k0 < 16; k0++) {
        int k = k0 * 8;
        float a0f = rowA0[k + tig];
        float a1f = rowA1[k + tig];
        float a2f = rowA0[k + tig + 4];
        float a3f = rowA1[k + tig + 4];
        uint32_t ah0, ah1, ah2, ah3, al0, al1, al2, al3;
        tf32_split(a0f, ah0, al0);
        tf32_split(a1f, ah1, al1);
        tf32_split(a2f, ah2, al2);
        tf32_split(a3f, ah3, al3);

        const float4* bp = Fr + (k0 * 16) * 32 + lane;

        #pragma unroll
        for (int nt = 0; nt < 16; nt++) {
            float4 f = __ldg(bp + nt * 32);
            uint32_t bh0 = __float_as_uint(f.x), bh1 = __float_as_uint(f.y);
            uint32_t bl0 = __float_as_uint(f.z), bl1 = __float_as_uint(f.w);
            MMA_TF32(acc[nt], ah0, ah1, ah2, ah3, bh0, bh1);
            MMA_TF32(acc[nt], ah0, ah1, ah2, ah3, bl0, bl1);
            MMA_TF32(acc[nt], al0, al1, al2, al3, bh0, bh1);
        }
    }

    // store: c0,c1 -> row g, cols 2tig,2tig+1; c2,c3 -> row g+8
    int r1 = row0 + warpRow + g;
    int r2 = r1 + 8;
    #pragma unroll
    for (int nt = 0; nt < 16; nt++) {
        int col = nt * 8 + tig * 2;
        if (r1 < n) *(float2*)(H + r1 * D + col) = make_float2(acc[nt][0], acc[nt][1]);
        if (r2 < n) *(float2*)(H + r2 * D + col) = make_float2(acc[nt][2], acc[nt][3]);
    }
}

// ---------------- fused gather + self-loop + bias + relu (atomic-free) ----------------
__global__ void gather_k(const float* __restrict__ bias) {
    int gt = blockIdx.x * blockDim.x + threadIdx.x;
    int c = gt >> 5;
    int lane = gt & 31;
    if (c >= N_NODES) return;

    int s = g_off[c];
    int e = g_off[c + 1];
    float4 acc = make_float4(0.f, 0.f, 0.f, 0.f);

    int i = s;
    for (; i + 4 <= e; i += 4) {
        float2 m0 = g_em[i + 0];
        float2 m1 = g_em[i + 1];
        float2 m2 = g_em[i + 2];
        float2 m3 = g_em[i + 3];
        const float4 v0 = *(const float4*)(g_h + (size_t)__float_as_int(m0.x) * D + lane * 4);
        const float4 v1 = *(const float4*)(g_h + (size_t)__float_as_int(m1.x) * D + lane * 4);
        const float4 v2 = *(const float4*)(g_h + (size_t)__float_as_int(m2.x) * D + lane * 4);
        const float4 v3 = *(const float4*)(g_h + (size_t)__float_as_int(m3.x) * D + lane * 4);
        acc.x += m0.y * v0.x + m1.y * v1.x + m2.y * v2.x + m3.y * v3.x;
        acc.y += m0.y * v0.y + m1.y * v1.y + m2.y * v2.y + m3.y * v3.y;
        acc.z += m0.y * v0.z + m1.y * v1.z + m2.y * v2.z + m3.y * v3.z;
        acc.w += m0.y * v0.w + m1.y * v1.w + m2.y * v2.w + m3.y * v3.w;
    }
    for (; i < e; i++) {
        float2 m = g_em[i];
        const float4 v = *(const float4*)(g_h + (size_t)__float_as_int(m.x) * D + lane * 4);
        acc.x += m.y * v.x; acc.y += m.y * v.y; acc.z += m.y * v.z; acc.w += m.y * v.w;
    }

    float d = g_dis[c];
    float d2 = d * d;
    float4 h = *(const float4*)(g_h + (size_t)c * D + lane * 4);
    float4 b = ((const float4*)bias)[lane];
    float4 o;
    o.x = fmaxf(acc.x + d2 * h.x + b.x, 0.f);
    o.y = fmaxf(acc.y + d2 * h.y + b.y, 0.f);
    o.z = fmaxf(acc.z + d2 * h.z + b.z, 0.f);
    o.w = fmaxf(acc.w + d2 * h.w + b.w, 0.f);
    *(float4*)(g_x + (size_t)c * D + lane * 4) = o;
}

// ---------------- pooling ----------------
__global__ void pool_k(const int* __restrict__ batch, const float* __restrict__ lw) {
    int gt = blockIdx.x * blockDim.x + threadIdx.x;
    int node = gt >> 5;
    int lane = gt & 31;
    if (node >= N_NODES) return;
    float4 xv = ((const float4*)g_x)[node * 32 + lane];
    float4 wv = ((const float4*)lw)[lane];
    float s = xv.x * wv.x + xv.y * wv.y + xv.z * wv.z + xv.w * wv.w;
    #pragma unroll
    for (int o = 16; o > 0; o >>= 1) s += __shfl_xor_sync(0xFFFFFFFFu, s, o);
    if (lane == 0) {
        int g = batch[node];
        atomicAdd(&g_gsum[g], s);
        atomicAdd(&g_gcnt[g], 1);
    }
}

__global__ void final_k(const float* __restrict__ lb, float* __restrict__ out) {
    int g = blockIdx.x * blockDim.x + threadIdx.x;
    if (g >= N_GRAPHS) return;
    float c = fmaxf((float)g_gcnt[g], 1.0f);
    out[g] = g_gsum[g] / c + lb[0];
}

// ---------------- launcher ----------------
extern "C" void kernel_launch(void* const* d_in, const int* in_sizes, int n_in,
                              void* d_out, int out_size) {
    const float* x    = (const float*)d_in[0];
    const int*   ei   = (const int*)d_in[1];    // int32 (JAX x64 disabled)
    const int*   bat  = (const int*)d_in[2];
    const float* Ws   = (const float*)d_in[3];
    const float* bs   = (const float*)d_in[4];
    const float* lw   = (const float*)d_in[5];
    const float* lb   = (const float*)d_in[6];
    float*       out  = (float*)d_out;

    const int gemm_smem = (128 * XS_STRIDE) * (int)sizeof(float);   // 67.6 KB

    static bool attr_set = false;
    if (!attr_set) {
        cudaFuncSetAttribute(gemm_tc_k, cudaFuncAttributeMaxDynamicSharedMemorySize,
                             gemm_smem);
        attr_set = true;
    }

    float *h_p, *x_p;
    float4 *wf_p;
    cudaGetSymbolAddress((void**)&h_p,  g_h);
    cudaGetSymbolAddress((void**)&x_p,  g_x);
    cudaGetSymbolAddress((void**)&wf_p, g_wf);

    // prep
    zero_misc_k<<<(N_NODES + 255) / 256, 256>>>();
    wfrag_k<<<(N_LAYERS * D * D + 255) / 256, 256>>>(Ws);
    deg_k<<<(N_EDGES + 255) / 256, 256>>>(ei);
    scan1_k<<<SCAN_NBLK, SCAN_BLK>>>();
    scan2_k<<<1, 32>>>();
    scan3_k<<<(N_NODES + 255) / 256, 256>>>();
    place_k<<<(N_EDGES + 255) / 256, 256>>>(ei);

    // layers
    const int gemm_blocks = (N_NODES + 127) / 128;
    const int gather_blocks = (N_NODES * 32 + 255) / 256;

    for (int l = 0; l < N_LAYERS; l++) {
        const float* xin = (l == 0) ? x : x_p;
        gemm_tc_k<<<gemm_blocks, 256, gemm_smem>>>(
            xin, wf_p + l * FRAG4_PER_LAYER, h_p, N_NODES);
        gather_k<<<gather_blocks, 256>>>(bs + l * D);
    }

    // pooling + output
    pool_k<<<(N_NODES * 32 + 255) / 256, 256>>>(bat, lw);
    final_k<<<(N_GRAPHS + 255) / 256, 256>>>(lb, out);
}